// round 7
// baseline (speedup 1.0000x reference)
#include <cuda_runtime.h>

#define NW      18
#define DIM     (1 << 18)
#define BATCH   64
#define GROUP   16             // batch elements per L2-resident group (2x32MB working set)
#define THREADS 512
#define TILE    8192           // amplitudes per CTA (u64 re/im pair -> 64 KB smem)
#define NACC    14             // 13 masked sums (bits 0..12) + total prob

typedef unsigned long long u64;

// Ping-pong state buffers (128 MB each). h: reads input/g_b, writes g_a.
// l: reads g_a, writes g_b (or fused exp-val on last layer).
__device__ u64    g_a[(size_t)BATCH * DIM];
__device__ u64    g_b[(size_t)BATCH * DIM];
__device__ float4 g_half[3][NW];   // cy, sy, cos(th_z/2), sin(th_z/2)
__device__ float2 g_full[3][NW];   // cos(th_z),  sin(th_z)
__device__ float  g_part[BATCH * 32 * NACC];

// ---- packed f32x2 helpers ---------------------------------------------------
static __device__ __forceinline__ u64 pk2(float x, float y) {
    u64 r; asm("mov.b64 %0,{%1,%2};" : "=l"(r) : "f"(x), "f"(y)); return r;
}
static __device__ __forceinline__ void up2(u64 a, float& x, float& y) {
    asm("mov.b64 {%0,%1},%2;" : "=f"(x), "=f"(y) : "l"(a));
}
static __device__ __forceinline__ u64 fma2_(u64 a, u64 b, u64 c) {
    u64 r; asm("fma.rn.f32x2 %0,%1,%2,%3;" : "=l"(r) : "l"(a), "l"(b), "l"(c)); return r;
}
static __device__ __forceinline__ u64 mul2_(u64 a, u64 b) {
    u64 r; asm("mul.rn.f32x2 %0,%1,%2;" : "=l"(r) : "l"(a), "l"(b)); return r;
}

// ---------------------------------------------------------------------------
__global__ void prep_kernel(const float* __restrict__ params) {
    int t = threadIdx.x;
    if (t < 3 * NW) {
        int l = t / NW, w = t % NW;
        float cy, sy, czh, szh, czf, szf;
        sincosf(0.5f * params[l * 36 + w],      &sy,  &cy);    // params[l,0,w]
        sincosf(0.5f * params[l * 36 + NW + w], &szh, &czh);   // params[l,1,w] half
        sincosf(params[l * 36 + NW + w],        &szf, &czf);   // full angle
        g_half[l][w] = make_float4(cy, sy, czh, szh);
        g_full[l][w] = make_float2(czf, szf);
    }
}

// Rotation coefficients for the register-pair path (RY half-angle + RZ full
// angle applied to the bit=0 amplitude only; global phase e^{+i th/2} dropped —
// valid because the output depends only on |amp|^2).
struct RC { u64 cy2, sy2, msy2; float cf, sf; };
static __device__ __forceinline__ RC mkrc(int l, int w) {
    float4 H = g_half[l][w]; float2 F = g_full[l][w];
    RC r;
    r.cy2  = pk2(H.x, H.x);
    r.sy2  = pk2(H.y, H.y);
    r.msy2 = pk2(-H.y, -H.y);
    r.cf = F.x; r.sf = F.y;
    return r;
}

// RY then RZ(global-phase-reduced) on a register pair (A: bit=0, B: bit=1).
static __device__ __forceinline__ void rp2p(u64& A, u64& B, const RC& r) {
    u64 nA = fma2_(r.cy2, A, mul2_(r.msy2, B));   // A' = cy*A - sy*B
    u64 nB = fma2_(r.sy2, A, mul2_(r.cy2,  B));   // B' = sy*A + cy*B
    float ax, ay; up2(nA, ax, ay);
    A = pk2(fmaf(ay, r.sf, ax * r.cf),            // A'' = A' * e^{-i th}
            fmaf(-ax, r.sf, ay * r.cf));
    B = nB;
}

// RY+RZ(+-half-angle) where the pair partner lives in lane ^ d.
static __device__ __forceinline__ void shrotp(u64& v, u64 cy2, u64 sgn2,
                                              float cz, float zs, int d) {
    float vx, vy; up2(v, vx, vy);
    float ox = __shfl_xor_sync(0xffffffffu, vx, d);
    float oy = __shfl_xor_sync(0xffffffffu, vy, d);
    u64 n = fma2_(cy2, v, mul2_(sgn2, pk2(ox, oy)));
    float nx, ny; up2(n, nx, ny);
    v = pk2(fmaf(zs, ny, nx * cz), fmaf(-zs, nx, ny * cz));
}

// Three register-bit rotations over v[8]: pairing strides 1, 2, 4.
static __device__ __forceinline__ void rot8p(u64 (&v)[8], int l, int wa, int wb, int wc) {
    { RC r = mkrc(l, wa); rp2p(v[0],v[1],r); rp2p(v[2],v[3],r); rp2p(v[4],v[5],r); rp2p(v[6],v[7],r); }
    { RC r = mkrc(l, wb); rp2p(v[0],v[2],r); rp2p(v[1],v[3],r); rp2p(v[4],v[6],r); rp2p(v[5],v[7],r); }
    { RC r = mkrc(l, wc); rp2p(v[0],v[4],r); rp2p(v[1],v[5],r); rp2p(v[2],v[6],r); rp2p(v[3],v[7],r); }
}

// ---------------------------------------------------------------------------
// H kernel: rotations on global bits 10..17 (wires 0..7).
// Tile bits {0..4} u {10..17}; chunk = bits 5..9. Read folds prior layer's
// low CNOT chain segment (targets 0..11). One swizzled SMEM transpose each way.
__global__ __launch_bounds__(THREADS, 2)
void h_kernel(const float* __restrict__ in_re, const float* __restrict__ in_im,
              int layer, int b0) {
    extern __shared__ u64 sm[];
    const int t = threadIdx.x, lane = t & 31, wrp = t >> 5;
    const int b = b0 + (blockIdx.x >> 5), chunk = blockIdx.x & 31;
    const size_t base = (size_t)b * DIM;
    const u64* __restrict__ src = g_b;

    if (layer == 0) {
#pragma unroll
        for (int i = 0; i < 16; i++) {
            int e = i * THREADS + t;
            int a = (e & 31) | (chunk << 5) | ((e >> 5) << 10);
            sm[e ^ ((e >> 5) & 31)] = pk2(in_re[base + a], in_im[base + a]);
        }
    } else {
#pragma unroll
        for (int i = 0; i < 16; i++) {
            int e = i * THREADS + t;
            int a = (e & 31) | (chunk << 5) | ((e >> 5) << 10);
            a ^= (a >> 1) & 0x0FFF;                 // fold: prior layer chain C(12..1)
            sm[e ^ ((e >> 5) & 31)] = src[base + a];
        }
    }
    __syncthreads();

    // lane = global bits 10..14 (wires 7..3) via shfl; regs = bits 15..17 (wires 2..0).
#pragma unroll
    for (int j = 0; j < 2; j++) {
        const int lo = wrp | (j << 4);
        u64 v[8];
#pragma unroll
        for (int r = 0; r < 8; r++)
            v[r] = sm[(lo ^ lane) | (lane << 5) | (r << 10)];
#pragma unroll
        for (int q = 0; q < 5; q++) {
            float4 T = g_half[layer][7 - q];
            int bit = (lane >> q) & 1;
            float sgn = bit ? T.y : -T.y;
            float zs  = bit ? -T.w : T.w;
            u64 cy2 = pk2(T.x, T.x), sgn2 = pk2(sgn, sgn);
#pragma unroll
            for (int r = 0; r < 8; r++) shrotp(v[r], cy2, sgn2, T.z, zs, 1 << q);
        }
        rot8p(v, layer, 2, 1, 0);
#pragma unroll
        for (int r = 0; r < 8; r++)
            sm[(lo ^ lane) | (lane << 5) | (r << 10)] = v[r];
    }
    __syncthreads();

#pragma unroll
    for (int i = 0; i < 16; i++) {
        int e = i * THREADS + t;
        int a = (e & 31) | (chunk << 5) | ((e >> 5) << 10);
        g_a[base + a] = sm[e ^ ((e >> 5) & 31)];
    }
}

// ---------------------------------------------------------------------------
// L kernel: rotations on global bits 0..9 (wires 17..8).
// Tile = contiguous bits 0..12; chunk = bits 13..17. Read folds this layer's
// high CNOT chain segment (targets 12..16). Phase 1: bits 0..4 via shfl,
// 5..7 in regs. One SMEM exchange. Phase 2: bits 8,9 in regs, then store
// (or fused exp-val with suffix-parity sign masks on the last layer).
__global__ __launch_bounds__(THREADS, 2)
void l_kernel(int layer, int last, int b0) {
    extern __shared__ u64 sm[];
    const int t = threadIdx.x, lane = t & 31, wrp = t >> 5;
    const int b = b0 + (blockIdx.x >> 5), chunk = blockIdx.x & 31;
    const size_t base = (size_t)b * DIM;
    const u64* __restrict__ src = g_a;

#pragma unroll
    for (int j = 0; j < 2; j++) {
        const int hi = (wrp | (j << 4)) << 8;
        u64 v[8];
#pragma unroll
        for (int r = 0; r < 8; r++) {
            int a = (chunk << 13) | lane | (r << 5) | hi;
            a ^= (a >> 1) & 0x1F000;                // fold: this layer chain C(17..13)
            v[r] = src[base + a];
        }
#pragma unroll
        for (int q = 0; q < 5; q++) {
            float4 T = g_half[layer][17 - q];
            int bit = (lane >> q) & 1;
            float sgn = bit ? T.y : -T.y;
            float zs  = bit ? -T.w : T.w;
            u64 cy2 = pk2(T.x, T.x), sgn2 = pk2(sgn, sgn);
#pragma unroll
            for (int r = 0; r < 8; r++) shrotp(v[r], cy2, sgn2, T.z, zs, 1 << q);
        }
        rot8p(v, layer, 12, 11, 10);
#pragma unroll
        for (int r = 0; r < 8; r++)
            sm[lane | (r << 5) | hi] = v[r];
    }
    __syncthreads();

    float acc[NACC];
    if (last)
#pragma unroll
        for (int i = 0; i < NACC; i++) acc[i] = 0.f;

    const RC rcb8 = mkrc(layer, 9);   // global bit 8 -> wire 9
    const RC rcb9 = mkrc(layer, 8);   // global bit 9 -> wire 8
#pragma unroll
    for (int u = 0; u < 4; u++) {
        const int ex = ((wrp & 7) << 5) | (((wrp >> 3) | (u << 1)) << 10);
        u64 v[4];
#pragma unroll
        for (int r = 0; r < 4; r++)
            v[r] = sm[lane | ex | ((r & 1) << 8) | ((r >> 1) << 9)];
        rp2p(v[0], v[1], rcb8); rp2p(v[2], v[3], rcb8);
        rp2p(v[0], v[2], rcb9); rp2p(v[1], v[3], rcb9);
        if (!last) {
#pragma unroll
            for (int r = 0; r < 4; r++) {
                int e = lane | ex | ((r & 1) << 8) | ((r >> 1) << 9);
                g_b[base + (size_t)((chunk << 13) | e)] = v[r];
            }
        } else {
#pragma unroll
            for (int r = 0; r < 4; r++) {
                int e = lane | ex | ((r & 1) << 8) | ((r >> 1) << 9);
                float vx, vy; up2(v[r], vx, vy);
                float pr = vx * vx + vy * vy;
                float prn = -pr;
                int p = e;                            // suffix parity: bit k = XOR e[k..12]
                p ^= p >> 1; p ^= p >> 2; p ^= p >> 4; p ^= p >> 8;
#pragma unroll
                for (int k = 0; k < 13; k++)
                    acc[k] += ((p >> k) & 1) ? prn : pr;
                acc[13] += pr;
            }
        }
    }

    if (last) {
#pragma unroll
        for (int i = 0; i < NACC; i++)
#pragma unroll
            for (int o = 16; o > 0; o >>= 1)
                acc[i] += __shfl_xor_sync(0xffffffffu, acc[i], o);
        __syncthreads();
        float* red = (float*)sm;
        if (lane == 0)
#pragma unroll
            for (int i = 0; i < NACC; i++) red[wrp * NACC + i] = acc[i];
        __syncthreads();
        if (t < NACC) {
            float s = 0.f;
            for (int w2 = 0; w2 < 16; w2++) s += red[w2 * NACC + t];
            g_part[(b * 32 + chunk) * NACC + t] = s;
        }
    }
}

// ---------------------------------------------------------------------------
__global__ void head_kernel(const float* __restrict__ head_w,
                            const float* __restrict__ head_b,
                            float* __restrict__ out) {
    int b = threadIdx.x;
    if (b >= BATCH) return;
    float fw[NW];
#pragma unroll
    for (int w = 0; w < NW; w++) fw[w] = 0.f;
    for (int c = 0; c < 32; c++) {
        const float* pp = &g_part[(b * 32 + c) * NACC];
#pragma unroll
        for (int k = 0; k < 13; k++) fw[17 - k] += pp[k];    // in-tile masks
        float sp = pp[13];
#pragma unroll
        for (int k = 13; k < 18; k++)                        // chunk-bit signs
            fw[17 - k] += ((c >> (k - 13)) & 1) ? -sp : sp;
    }
    float o = head_b[0];
#pragma unroll
    for (int w = 0; w < NW; w++) o += fw[w] * head_w[w];
    out[b] = o;
}

// ---------------------------------------------------------------------------
extern "C" void kernel_launch(void* const* d_in, const int* in_sizes, int n_in,
                              void* d_out, int out_size) {
    const float* state_re = (const float*)d_in[0];
    const float* state_im = (const float*)d_in[1];
    const float* params   = (const float*)d_in[2];
    const float* head_w   = (const float*)d_in[3];
    const float* head_b   = (const float*)d_in[4];
    float* out = (float*)d_out;

    const int smem = TILE * sizeof(u64);   // 64 KB
    cudaFuncSetAttribute(h_kernel, cudaFuncAttributeMaxDynamicSharedMemorySize, smem);
    cudaFuncSetAttribute(l_kernel, cudaFuncAttributeMaxDynamicSharedMemorySize, smem);

    prep_kernel<<<1, 64>>>(params);
    // L2-resident scheduling: fully process GROUP batch elements (working set
    // 2 x GROUP x 2MB = 64MB, fits in 126MB L2) through all layers before the
    // next group. Groups are disjoint batch slices -> order-independent.
    for (int b0 = 0; b0 < BATCH; b0 += GROUP) {
        for (int l = 0; l < 3; l++) {
            h_kernel<<<GROUP * 32, THREADS, smem>>>(state_re, state_im, l, b0);
            l_kernel<<<GROUP * 32, THREADS, smem>>>(l, l == 2, b0);
        }
    }
    head_kernel<<<1, BATCH>>>(head_w, head_b, out);
}

// round 8
// speedup vs baseline: 1.2913x; 1.2913x over previous
#include <cuda_runtime.h>

#define NW      18
#define DIM     (1 << 18)
#define BATCH   64
#define THREADS 512
#define TILE    8192           // amplitudes per CTA (u64 re/im pair -> 64 KB smem)
#define NACC    14             // 13 masked sums (bits 0..12) + total prob

typedef unsigned long long u64;

// Ping-pong state buffers (128 MB each). h: reads input/g_b, writes g_a.
// l: reads g_a, writes g_b (or fused exp-val on last layer).
__device__ u64    g_a[(size_t)BATCH * DIM];
__device__ u64    g_b[(size_t)BATCH * DIM];
__device__ float2 g_ry[3][NW];          // cos(th_y/2), sin(th_y/2)
__device__ u64    g_phz_h[3][256];      // deferred RZ phase e^{-iA}, h rotation bits
__device__ u64    g_phz_l[3][1024];     // deferred RZ phase e^{-iA}, l rotation bits
__device__ float  g_part[BATCH * 32 * NACC];

// ---- packed f32x2 helpers ---------------------------------------------------
static __device__ __forceinline__ u64 pk2(float x, float y) {
    u64 r; asm("mov.b64 %0,{%1,%2};" : "=l"(r) : "f"(x), "f"(y)); return r;
}
static __device__ __forceinline__ void up2(u64 a, float& x, float& y) {
    asm("mov.b64 {%0,%1},%2;" : "=f"(x), "=f"(y) : "l"(a));
}
static __device__ __forceinline__ u64 fma2_(u64 a, u64 b, u64 c) {
    u64 r; asm("fma.rn.f32x2 %0,%1,%2,%3;" : "=l"(r) : "l"(a), "l"(b), "l"(c)); return r;
}
static __device__ __forceinline__ u64 mul2_(u64 a, u64 b) {
    u64 r; asm("mul.rn.f32x2 %0,%1,%2;" : "=l"(r) : "l"(a), "l"(b)); return r;
}

// ---------------------------------------------------------------------------
// prep: RY half-angle coefficients + deferred-RZ phase tables.
// RZ(th) ~ diag(e^{-i th}, 1) up to a global phase (output depends on |amp|^2).
// Per kernel, all its RZs commute past all its RYs (disjoint bits) -> one
// diagonal phase e^{-iA}, A = sum of th_z over rotation bits that are 0.
__global__ void prep_kernel(const float* __restrict__ params) {
    int t = threadIdx.x;
    if (t < 3 * NW) {
        int l = t / NW, w = t % NW;
        float cy, sy;
        sincosf(0.5f * params[l * 36 + w], &sy, &cy);
        g_ry[l][w] = make_float2(cy, sy);
    }
    // h tables: idx bit j (0..7) <-> global bit 10+j <-> wire 7-j
    for (int i = t; i < 3 * 256; i += blockDim.x) {
        int l = i >> 8, idx = i & 255;
        float A = 0.f;
        for (int j = 0; j < 8; j++)
            if (!((idx >> j) & 1)) A += params[l * 36 + NW + (7 - j)];
        float s, c; sincosf(A, &s, &c);
        g_phz_h[l][idx] = pk2(c, -s);
    }
    // l tables: idx bit j (0..9) <-> global bit j <-> wire 17-j
    for (int i = t; i < 3 * 1024; i += blockDim.x) {
        int l = i >> 10, idx = i & 1023;
        float A = 0.f;
        for (int j = 0; j < 10; j++)
            if (!((idx >> j) & 1)) A += params[l * 36 + NW + (17 - j)];
        float s, c; sincosf(A, &s, &c);
        g_phz_l[l][idx] = pk2(c, -s);
    }
}

// RY on a register pair (A: bit=0, B: bit=1).
static __device__ __forceinline__ void rp2y(u64& A, u64& B, u64 cy2, u64 sy2, u64 msy2) {
    u64 nA = fma2_(cy2, A, mul2_(msy2, B));   // A' = cy*A - sy*B
    u64 nB = fma2_(sy2, A, mul2_(cy2,  B));   // B' = sy*A + cy*B
    A = nA; B = nB;
}

// RY where the pair partner lives in lane ^ d.
static __device__ __forceinline__ void shroty(u64& v, u64 cy2, u64 sgn2, int d) {
    float vx, vy; up2(v, vx, vy);
    float ox = __shfl_xor_sync(0xffffffffu, vx, d);
    float oy = __shfl_xor_sync(0xffffffffu, vy, d);
    v = fma2_(cy2, v, mul2_(sgn2, pk2(ox, oy)));
}

// v * (pc + i*ps), p = pk2(pc, ps).
static __device__ __forceinline__ u64 cmulp(u64 v, u64 p) {
    float x, y, pc, ps; up2(v, x, y); up2(p, pc, ps);
    return pk2(fmaf(-y, ps, x * pc), fmaf(x, ps, y * pc));
}

// Three register-bit RYs over v[8]: pairing strides 1, 2, 4.
static __device__ __forceinline__ void rot8y(u64 (&v)[8], int l, int wa, int wb, int wc) {
    float2 W;
    W = g_ry[l][wa];
    { u64 c = pk2(W.x, W.x), s = pk2(W.y, W.y), m = pk2(-W.y, -W.y);
      rp2y(v[0],v[1],c,s,m); rp2y(v[2],v[3],c,s,m); rp2y(v[4],v[5],c,s,m); rp2y(v[6],v[7],c,s,m); }
    W = g_ry[l][wb];
    { u64 c = pk2(W.x, W.x), s = pk2(W.y, W.y), m = pk2(-W.y, -W.y);
      rp2y(v[0],v[2],c,s,m); rp2y(v[1],v[3],c,s,m); rp2y(v[4],v[6],c,s,m); rp2y(v[5],v[7],c,s,m); }
    W = g_ry[l][wc];
    { u64 c = pk2(W.x, W.x), s = pk2(W.y, W.y), m = pk2(-W.y, -W.y);
      rp2y(v[0],v[4],c,s,m); rp2y(v[1],v[5],c,s,m); rp2y(v[2],v[6],c,s,m); rp2y(v[3],v[7],c,s,m); }
}

// ---------------------------------------------------------------------------
// H kernel: RYs on global bits 10..17 (wires 0..7) + one deferred phase.
// Tile bits {0..4} u {10..17}; chunk = bits 5..9. Read folds prior layer's
// low CNOT chain segment (targets 0..11). One swizzled SMEM transpose each way.
// Layer 2's phase is skipped: it commutes (as a diagonal) through everything
// remaining and cancels in |amp|^2.
__global__ __launch_bounds__(THREADS, 2)
void h_kernel(const float* __restrict__ in_re, const float* __restrict__ in_im, int layer) {
    extern __shared__ u64 sm[];
    const int t = threadIdx.x, lane = t & 31, wrp = t >> 5;
    const int b = blockIdx.x >> 5, chunk = blockIdx.x & 31;
    const size_t base = (size_t)b * DIM;

    if (layer == 0) {
#pragma unroll
        for (int i = 0; i < 16; i++) {
            int e = i * THREADS + t;
            int a = (e & 31) | (chunk << 5) | ((e >> 5) << 10);
            sm[e ^ ((e >> 5) & 31)] = pk2(in_re[base + a], in_im[base + a]);
        }
    } else {
#pragma unroll
        for (int i = 0; i < 16; i++) {
            int e = i * THREADS + t;
            int a = (e & 31) | (chunk << 5) | ((e >> 5) << 10);
            a ^= (a >> 1) & 0x0FFF;                 // fold: prior layer chain C(12..1)
            sm[e ^ ((e >> 5) & 31)] = g_b[base + a];
        }
    }
    __syncthreads();

    // lane = global bits 10..14 (wires 7..3) via shfl; regs = bits 15..17 (wires 2..0).
#pragma unroll
    for (int j = 0; j < 2; j++) {
        const int lo = wrp | (j << 4);
        u64 v[8];
#pragma unroll
        for (int r = 0; r < 8; r++)
            v[r] = sm[(lo ^ lane) | (lane << 5) | (r << 10)];
#pragma unroll
        for (int q = 0; q < 5; q++) {
            float2 W = g_ry[layer][7 - q];
            float sgn = ((lane >> q) & 1) ? W.y : -W.y;
            u64 cy2 = pk2(W.x, W.x), sgn2 = pk2(sgn, sgn);
#pragma unroll
            for (int r = 0; r < 8; r++) shroty(v[r], cy2, sgn2, 1 << q);
        }
        rot8y(v, layer, 2, 1, 0);
        if (layer != 2) {            // deferred RZ phase (rotation bits = lane | r<<5)
#pragma unroll
            for (int r = 0; r < 8; r++)
                v[r] = cmulp(v[r], g_phz_h[layer][lane | (r << 5)]);
        }
#pragma unroll
        for (int r = 0; r < 8; r++)
            sm[(lo ^ lane) | (lane << 5) | (r << 10)] = v[r];
    }
    __syncthreads();

#pragma unroll
    for (int i = 0; i < 16; i++) {
        int e = i * THREADS + t;
        int a = (e & 31) | (chunk << 5) | ((e >> 5) << 10);
        g_a[base + a] = sm[e ^ ((e >> 5) & 31)];
    }
}

// ---------------------------------------------------------------------------
// L kernel: RYs on global bits 0..9 (wires 17..8) + one deferred phase.
// Tile = contiguous bits 0..12; chunk = bits 13..17 (blockIdx REVERSED for
// L2 reuse of the producer's most-recent writes). Read folds this layer's
// high CNOT chain segment (targets 12..16). Phase 1: bits 0..4 via shfl,
// 5..7 in regs. One SMEM exchange. Phase 2: bits 8,9 in regs, then phase +
// store (or fused exp-val with suffix-parity sign masks on the last layer —
// deferred phase skipped there, it cancels in |amp|^2).
__global__ __launch_bounds__(THREADS, 2)
void l_kernel(int layer, int last) {
    extern __shared__ u64 sm[];
    const int t = threadIdx.x, lane = t & 31, wrp = t >> 5;
    const int rbi = (BATCH * 32 - 1) - blockIdx.x;       // boustrophedon
    const int b = rbi >> 5, chunk = rbi & 31;
    const size_t base = (size_t)b * DIM;

#pragma unroll
    for (int j = 0; j < 2; j++) {
        const int hi = (wrp | (j << 4)) << 8;
        u64 v[8];
#pragma unroll
        for (int r = 0; r < 8; r++) {
            int a = (chunk << 13) | lane | (r << 5) | hi;
            a ^= (a >> 1) & 0x1F000;                // fold: this layer chain C(17..13)
            v[r] = g_a[base + a];
        }
#pragma unroll
        for (int q = 0; q < 5; q++) {
            float2 W = g_ry[layer][17 - q];
            float sgn = ((lane >> q) & 1) ? W.y : -W.y;
            u64 cy2 = pk2(W.x, W.x), sgn2 = pk2(sgn, sgn);
#pragma unroll
            for (int r = 0; r < 8; r++) shroty(v[r], cy2, sgn2, 1 << q);
        }
        rot8y(v, layer, 12, 11, 10);
#pragma unroll
        for (int r = 0; r < 8; r++)
            sm[lane | (r << 5) | hi] = v[r];
    }
    __syncthreads();

    float acc[NACC];
    if (last)
#pragma unroll
        for (int i = 0; i < NACC; i++) acc[i] = 0.f;

    float2 W8 = g_ry[layer][9];   // global bit 8 -> wire 9
    float2 W9 = g_ry[layer][8];   // global bit 9 -> wire 8
    const u64 c8 = pk2(W8.x, W8.x), s8 = pk2(W8.y, W8.y), m8 = pk2(-W8.y, -W8.y);
    const u64 c9 = pk2(W9.x, W9.x), s9 = pk2(W9.y, W9.y), m9 = pk2(-W9.y, -W9.y);
#pragma unroll
    for (int u = 0; u < 4; u++) {
        const int ex = ((wrp & 7) << 5) | (((wrp >> 3) | (u << 1)) << 10);
        u64 v[4];
#pragma unroll
        for (int r = 0; r < 4; r++)
            v[r] = sm[lane | ex | ((r & 1) << 8) | ((r >> 1) << 9)];
        rp2y(v[0], v[1], c8, s8, m8); rp2y(v[2], v[3], c8, s8, m8);
        rp2y(v[0], v[2], c9, s9, m9); rp2y(v[1], v[3], c9, s9, m9);
        if (!last) {
#pragma unroll
            for (int r = 0; r < 4; r++) {
                int e = lane | ex | ((r & 1) << 8) | ((r >> 1) << 9);
                u64 w = cmulp(v[r], g_phz_l[layer][e & 1023]);   // deferred RZ phase
                g_b[base + (size_t)((chunk << 13) | e)] = w;
            }
        } else {
#pragma unroll
            for (int r = 0; r < 4; r++) {
                int e = lane | ex | ((r & 1) << 8) | ((r >> 1) << 9);
                float vx, vy; up2(v[r], vx, vy);
                float pr = vx * vx + vy * vy;
                float prn = -pr;
                int p = e;                            // suffix parity: bit k = XOR e[k..12]
                p ^= p >> 1; p ^= p >> 2; p ^= p >> 4; p ^= p >> 8;
#pragma unroll
                for (int k = 0; k < 13; k++)
                    acc[k] += ((p >> k) & 1) ? prn : pr;
                acc[13] += pr;
            }
        }
    }

    if (last) {
#pragma unroll
        for (int i = 0; i < NACC; i++)
#pragma unroll
            for (int o = 16; o > 0; o >>= 1)
                acc[i] += __shfl_xor_sync(0xffffffffu, acc[i], o);
        __syncthreads();
        float* red = (float*)sm;
        if (lane == 0)
#pragma unroll
            for (int i = 0; i < NACC; i++) red[wrp * NACC + i] = acc[i];
        __syncthreads();
        if (t < NACC) {
            float s = 0.f;
            for (int w2 = 0; w2 < 16; w2++) s += red[w2 * NACC + t];
            g_part[(b * 32 + chunk) * NACC + t] = s;
        }
    }
}

// ---------------------------------------------------------------------------
__global__ void head_kernel(const float* __restrict__ head_w,
                            const float* __restrict__ head_b,
                            float* __restrict__ out) {
    int b = threadIdx.x;
    if (b >= BATCH) return;
    float fw[NW];
#pragma unroll
    for (int w = 0; w < NW; w++) fw[w] = 0.f;
    for (int c = 0; c < 32; c++) {
        const float* pp = &g_part[(b * 32 + c) * NACC];
#pragma unroll
        for (int k = 0; k < 13; k++) fw[17 - k] += pp[k];    // in-tile masks
        float sp = pp[13];
#pragma unroll
        for (int k = 13; k < 18; k++)                        // chunk-bit signs
            fw[17 - k] += ((c >> (k - 13)) & 1) ? -sp : sp;
    }
    float o = head_b[0];
#pragma unroll
    for (int w = 0; w < NW; w++) o += fw[w] * head_w[w];
    out[b] = o;
}

// ---------------------------------------------------------------------------
extern "C" void kernel_launch(void* const* d_in, const int* in_sizes, int n_in,
                              void* d_out, int out_size) {
    const float* state_re = (const float*)d_in[0];
    const float* state_im = (const float*)d_in[1];
    const float* params   = (const float*)d_in[2];
    const float* head_w   = (const float*)d_in[3];
    const float* head_b   = (const float*)d_in[4];
    float* out = (float*)d_out;

    const int smem = TILE * sizeof(u64);   // 64 KB
    cudaFuncSetAttribute(h_kernel, cudaFuncAttributeMaxDynamicSharedMemorySize, smem);
    cudaFuncSetAttribute(l_kernel, cudaFuncAttributeMaxDynamicSharedMemorySize, smem);

    prep_kernel<<<1, 1024>>>(params);
    for (int l = 0; l < 3; l++) {
        h_kernel<<<BATCH * 32, THREADS, smem>>>(state_re, state_im, l);
        l_kernel<<<BATCH * 32, THREADS, smem>>>(l, l == 2);
    }
    head_kernel<<<1, BATCH>>>(head_w, head_b, out);
}

// round 9
// speedup vs baseline: 1.4026x; 1.0862x over previous
#include <cuda_runtime.h>

#define NW      18
#define DIM     (1 << 18)
#define BATCH   64
#define THREADS 512
#define TILE    8192           // amplitudes per CTA (u64 re/im pair -> 64 KB smem)
#define NACC    14             // 13 masked sums (bits 0..12) + total prob

typedef unsigned long long u64;
typedef ulonglong2 u64x2;

// Ping-pong state buffers (128 MB each). h: reads input/g_b, writes g_a.
// l: reads g_a, writes g_b (or fused exp-val on last layer).
__device__ u64    g_a[(size_t)BATCH * DIM];
__device__ u64    g_b[(size_t)BATCH * DIM];
__device__ float2 g_ry[3][NW];          // cos(th_y/2), sin(th_y/2)
__device__ u64    g_phz_h[3][256];      // deferred RZ phase e^{-iA}, h rotation bits
__device__ u64    g_phz_l[3][1024];     // deferred RZ phase e^{-iA}, l rotation bits
__device__ float  g_part[BATCH * 32 * NACC];

// ---- packed f32x2 helpers ---------------------------------------------------
static __device__ __forceinline__ u64 pk2(float x, float y) {
    u64 r; asm("mov.b64 %0,{%1,%2};" : "=l"(r) : "f"(x), "f"(y)); return r;
}
static __device__ __forceinline__ void up2(u64 a, float& x, float& y) {
    asm("mov.b64 {%0,%1},%2;" : "=f"(x), "=f"(y) : "l"(a));
}
static __device__ __forceinline__ u64 fma2_(u64 a, u64 b, u64 c) {
    u64 r; asm("fma.rn.f32x2 %0,%1,%2,%3;" : "=l"(r) : "l"(a), "l"(b), "l"(c)); return r;
}
static __device__ __forceinline__ u64 mul2_(u64 a, u64 b) {
    u64 r; asm("mul.rn.f32x2 %0,%1,%2;" : "=l"(r) : "l"(a), "l"(b)); return r;
}

// ---------------------------------------------------------------------------
__global__ void prep_kernel(const float* __restrict__ params) {
    int t = threadIdx.x;
    if (t < 3 * NW) {
        int l = t / NW, w = t % NW;
        float cy, sy;
        sincosf(0.5f * params[l * 36 + w], &sy, &cy);
        g_ry[l][w] = make_float2(cy, sy);
    }
    // h tables: idx bit j (0..7) <-> global bit 10+j <-> wire 7-j
    for (int i = t; i < 3 * 256; i += blockDim.x) {
        int l = i >> 8, idx = i & 255;
        float A = 0.f;
        for (int j = 0; j < 8; j++)
            if (!((idx >> j) & 1)) A += params[l * 36 + NW + (7 - j)];
        float s, c; sincosf(A, &s, &c);
        g_phz_h[l][idx] = pk2(c, -s);
    }
    // l tables: idx bit j (0..9) <-> global bit j <-> wire 17-j
    for (int i = t; i < 3 * 1024; i += blockDim.x) {
        int l = i >> 10, idx = i & 1023;
        float A = 0.f;
        for (int j = 0; j < 10; j++)
            if (!((idx >> j) & 1)) A += params[l * 36 + NW + (17 - j)];
        float s, c; sincosf(A, &s, &c);
        g_phz_l[l][idx] = pk2(c, -s);
    }
}

// RY on a register pair (A: bit=0, B: bit=1).
static __device__ __forceinline__ void rp2y(u64& A, u64& B, u64 cy2, u64 sy2, u64 msy2) {
    u64 nA = fma2_(cy2, A, mul2_(msy2, B));   // A' = cy*A - sy*B
    u64 nB = fma2_(sy2, A, mul2_(cy2,  B));   // B' = sy*A + cy*B
    A = nA; B = nB;
}

// RY where the pair partner lives in lane ^ d.
static __device__ __forceinline__ void shroty(u64& v, u64 cy2, u64 sgn2, int d) {
    float vx, vy; up2(v, vx, vy);
    float ox = __shfl_xor_sync(0xffffffffu, vx, d);
    float oy = __shfl_xor_sync(0xffffffffu, vy, d);
    v = fma2_(cy2, v, mul2_(sgn2, pk2(ox, oy)));
}

// v * (pc + i*ps), p = pk2(pc, ps).
static __device__ __forceinline__ u64 cmulp(u64 v, u64 p) {
    float x, y, pc, ps; up2(v, x, y); up2(p, pc, ps);
    return pk2(fmaf(-y, ps, x * pc), fmaf(x, ps, y * pc));
}

// RY over register-index bit `stride` on both halves of the bit-0 pairs.
static __device__ __forceinline__ void rotpairs(u64* vl, u64* vh, int stride, float2 W) {
    u64 c = pk2(W.x, W.x), s = pk2(W.y, W.y), m = pk2(-W.y, -W.y);
#pragma unroll
    for (int i = 0; i < 8; i++)
        if (!(i & stride)) {
            rp2y(vl[i], vl[i | stride], c, s, m);
            rp2y(vh[i], vh[i | stride], c, s, m);
        }
}

// h-kernel SMEM swizzle: XOR bits 1..4 with bits 5..8 (preserves bit 0 pairs).
static __device__ __forceinline__ int swz(int e) { return e ^ (((e >> 5) & 15) << 1); }

// ---------------------------------------------------------------------------
// H kernel: RYs on global bits 10..17 (wires 0..7) + one deferred phase.
// Tile bits {0..4} u {10..17}; chunk = bits 5..9. Read folds prior layer's
// low CNOT chain segment (targets 0..11; fold touches bit 0 -> scalar loads).
// Compute layout: bit0 pair in-reg, e[1..4]=wrp, e[5..9]=lane (g10..14, shfl),
// e[10..12]=reg (g15..17). All SMEM round trips 128-bit.
__global__ __launch_bounds__(THREADS, 2)
void h_kernel(const float* __restrict__ in_re, const float* __restrict__ in_im, int layer) {
    extern __shared__ u64 sm[];
    const int t = threadIdx.x, lane = t & 31, wrp = t >> 5;
    const int b = blockIdx.x >> 5, chunk = blockIdx.x & 31;
    const size_t base = (size_t)b * DIM;

    if (layer == 0) {
#pragma unroll
        for (int i = 0; i < 8; i++) {
            int e = (i * THREADS + t) * 2;                   // pair base (bit0=0)
            int a = (e & 31) | (chunk << 5) | ((e >> 5) << 10);
            float2 r2 = *(const float2*)(in_re + base + a);
            float2 i2 = *(const float2*)(in_im + base + a);
            u64x2 p; p.x = pk2(r2.x, i2.x); p.y = pk2(r2.y, i2.y);
            *(u64x2*)&sm[swz(e)] = p;
        }
    } else {
#pragma unroll
        for (int i = 0; i < 16; i++) {
            int e = i * THREADS + t;
            int a = (e & 31) | (chunk << 5) | ((e >> 5) << 10);
            a ^= (a >> 1) & 0x0FFF;                 // fold: prior layer chain C(12..1)
            sm[swz(e)] = g_b[base + a];
        }
    }
    __syncthreads();

    u64 vl[8], vh[8];
#pragma unroll
    for (int r = 0; r < 8; r++) {
        u64x2 p = *(u64x2*)&sm[swz((wrp << 1) | (lane << 5) | (r << 10))];
        vl[r] = p.x; vh[r] = p.y;
    }
#pragma unroll
    for (int q = 0; q < 5; q++) {                   // g10..14 = wires 7..3
        float2 W = g_ry[layer][7 - q];
        float sgn = ((lane >> q) & 1) ? W.y : -W.y;
        u64 cy2 = pk2(W.x, W.x), sgn2 = pk2(sgn, sgn);
#pragma unroll
        for (int r = 0; r < 8; r++) { shroty(vl[r], cy2, sgn2, 1 << q); shroty(vh[r], cy2, sgn2, 1 << q); }
    }
    rotpairs(vl, vh, 1, g_ry[layer][2]);            // g15 = wire 2
    rotpairs(vl, vh, 2, g_ry[layer][1]);            // g16 = wire 1
    rotpairs(vl, vh, 4, g_ry[layer][0]);            // g17 = wire 0
    if (layer != 2) {                               // deferred RZ phase, shared per pair
#pragma unroll
        for (int r = 0; r < 8; r++) {
            u64 ph = g_phz_h[layer][lane | (r << 5)];
            vl[r] = cmulp(vl[r], ph); vh[r] = cmulp(vh[r], ph);
        }
    }
#pragma unroll
    for (int r = 0; r < 8; r++) {
        u64x2 p; p.x = vl[r]; p.y = vh[r];
        *(u64x2*)&sm[swz((wrp << 1) | (lane << 5) | (r << 10))] = p;
    }
    __syncthreads();

#pragma unroll
    for (int i = 0; i < 8; i++) {
        int e = (i * THREADS + t) * 2;
        u64x2 p = *(u64x2*)&sm[swz(e)];
        int a = (e & 31) | (chunk << 5) | ((e >> 5) << 10);
        *(u64x2*)&g_a[base + a] = p;
    }
}

// ---------------------------------------------------------------------------
// L kernel: RYs on global bits 0..9 (wires 17..8) + one deferred phase.
// Tile = contiguous bits 0..12; chunk = bits 13..17 (blockIdx REVERSED for
// L2 reuse). Read folds this layer's high chain segment (targets 12..16 —
// bit0 pairs survive -> LDG.128). Phase 1: bit0 intra (wire 17, no shfl),
// bits 1..5 = lane (wires 16..12), bits 6..8 = regs (wires 11..9). One
// 128-bit SMEM exchange. Phase 2: bit 9 (wire 8) in regs, then phase+store
// (or fused exp-val; phase cancels in |amp|^2 on the last layer).
__global__ __launch_bounds__(THREADS, 2)
void l_kernel(int layer, int last) {
    extern __shared__ u64 sm[];
    const int t = threadIdx.x, lane = t & 31, wrp = t >> 5;
    const int rbi = (BATCH * 32 - 1) - blockIdx.x;       // boustrophedon
    const int b = rbi >> 5, chunk = rbi & 31;
    const size_t base = (size_t)b * DIM;

    u64 vl[8], vh[8];
#pragma unroll
    for (int r = 0; r < 8; r++) {
        int e = (wrp << 9) | (r << 6) | (lane << 1);
        int a = (chunk << 13) | e;
        a ^= (a >> 1) & 0x1F000;                // fold: this layer chain C(17..13)
        u64x2 p = *(const u64x2*)&g_a[base + a];
        vl[r] = p.x; vh[r] = p.y;
    }
    {   // bit 0 = wire 17: intra-pair, zero shfl
        float2 W = g_ry[layer][17];
        u64 c = pk2(W.x, W.x), s = pk2(W.y, W.y), m = pk2(-W.y, -W.y);
#pragma unroll
        for (int r = 0; r < 8; r++) rp2y(vl[r], vh[r], c, s, m);
    }
#pragma unroll
    for (int q = 0; q < 5; q++) {               // e[1+q] = g bit 1+q = wire 16-q
        float2 W = g_ry[layer][16 - q];
        float sgn = ((lane >> q) & 1) ? W.y : -W.y;
        u64 cy2 = pk2(W.x, W.x), sgn2 = pk2(sgn, sgn);
#pragma unroll
        for (int r = 0; r < 8; r++) { shroty(vl[r], cy2, sgn2, 1 << q); shroty(vh[r], cy2, sgn2, 1 << q); }
    }
    rotpairs(vl, vh, 1, g_ry[layer][11]);       // e6 = wire 11
    rotpairs(vl, vh, 2, g_ry[layer][10]);       // e7 = wire 10
    rotpairs(vl, vh, 4, g_ry[layer][9]);        // e8 = wire 9
#pragma unroll
    for (int r = 0; r < 8; r++) {
        u64x2 p; p.x = vl[r]; p.y = vh[r];
        *(u64x2*)&sm[(wrp << 9) | (r << 6) | (lane << 1)] = p;
    }
    __syncthreads();

    // Phase 2: e[9,11,12] in regs, e[6,7,8,10] = wrp.
    u64 wl[8], wh[8];
    const int e2b = (lane << 1) | ((wrp & 7) << 6) | ((wrp >> 3) << 10);
#pragma unroll
    for (int r = 0; r < 8; r++) {
        int e2 = e2b | ((r & 1) << 9) | (((r >> 1) & 1) << 11) | (((r >> 2) & 1) << 12);
        u64x2 p = *(u64x2*)&sm[e2];
        wl[r] = p.x; wh[r] = p.y;
    }
    {   // bit 9 = wire 8: reg-index bit 0
        float2 W = g_ry[layer][8];
        u64 c = pk2(W.x, W.x), s = pk2(W.y, W.y), m = pk2(-W.y, -W.y);
#pragma unroll
        for (int i = 0; i < 8; i += 2) { rp2y(wl[i], wl[i | 1], c, s, m); rp2y(wh[i], wh[i | 1], c, s, m); }
    }

    if (!last) {
#pragma unroll
        for (int r = 0; r < 8; r++) {
            int e2 = e2b | ((r & 1) << 9) | (((r >> 1) & 1) << 11) | (((r >> 2) & 1) << 12);
            u64x2 p;
            p.x = cmulp(wl[r], g_phz_l[layer][e2 & 1023]);        // pair halves differ in bit 0
            p.y = cmulp(wh[r], g_phz_l[layer][(e2 | 1) & 1023]);
            *(u64x2*)&g_b[base + (size_t)((chunk << 13) | e2)] = p;
        }
    } else {
        float acc[NACC];
#pragma unroll
        for (int i = 0; i < NACC; i++) acc[i] = 0.f;
#pragma unroll
        for (int r = 0; r < 8; r++) {
            int e2 = e2b | ((r & 1) << 9) | (((r >> 1) & 1) << 11) | (((r >> 2) & 1) << 12);
            float lx, ly, hx, hy;
            up2(wl[r], lx, ly); up2(wh[r], hx, hy);
            float prl = lx * lx + ly * ly;
            float prh = hx * hx + hy * hy;
            float sum = prl + prh, dif = prl - prh;
            int p = e2;                           // suffix parity: bit k = XOR e[k..12]
            p ^= p >> 1; p ^= p >> 2; p ^= p >> 4; p ^= p >> 8;
            acc[0] += (p & 1) ? -dif : dif;       // halves differ only in parity bit 0
#pragma unroll
            for (int k = 1; k < 13; k++)
                acc[k] += ((p >> k) & 1) ? -sum : sum;
            acc[13] += sum;
        }
#pragma unroll
        for (int i = 0; i < NACC; i++)
#pragma unroll
            for (int o = 16; o > 0; o >>= 1)
                acc[i] += __shfl_xor_sync(0xffffffffu, acc[i], o);
        __syncthreads();
        float* red = (float*)sm;
        if (lane == 0)
#pragma unroll
            for (int i = 0; i < NACC; i++) red[wrp * NACC + i] = acc[i];
        __syncthreads();
        if (t < NACC) {
            float s = 0.f;
            for (int w2 = 0; w2 < 16; w2++) s += red[w2 * NACC + t];
            g_part[(b * 32 + chunk) * NACC + t] = s;
        }
    }
}

// ---------------------------------------------------------------------------
__global__ void head_kernel(const float* __restrict__ head_w,
                            const float* __restrict__ head_b,
                            float* __restrict__ out) {
    int b = threadIdx.x;
    if (b >= BATCH) return;
    float fw[NW];
#pragma unroll
    for (int w = 0; w < NW; w++) fw[w] = 0.f;
    for (int c = 0; c < 32; c++) {
        const float* pp = &g_part[(b * 32 + c) * NACC];
#pragma unroll
        for (int k = 0; k < 13; k++) fw[17 - k] += pp[k];    // in-tile masks
        float sp = pp[13];
#pragma unroll
        for (int k = 13; k < 18; k++)                        // chunk-bit signs
            fw[17 - k] += ((c >> (k - 13)) & 1) ? -sp : sp;
    }
    float o = head_b[0];
#pragma unroll
    for (int w = 0; w < NW; w++) o += fw[w] * head_w[w];
    out[b] = o;
}

// ---------------------------------------------------------------------------
extern "C" void kernel_launch(void* const* d_in, const int* in_sizes, int n_in,
                              void* d_out, int out_size) {
    const float* state_re = (const float*)d_in[0];
    const float* state_im = (const float*)d_in[1];
    const float* params   = (const float*)d_in[2];
    const float* head_w   = (const float*)d_in[3];
    const float* head_b   = (const float*)d_in[4];
    float* out = (float*)d_out;

    const int smem = TILE * sizeof(u64);   // 64 KB
    cudaFuncSetAttribute(h_kernel, cudaFuncAttributeMaxDynamicSharedMemorySize, smem);
    cudaFuncSetAttribute(l_kernel, cudaFuncAttributeMaxDynamicSharedMemorySize, smem);

    prep_kernel<<<1, 1024>>>(params);
    for (int l = 0; l < 3; l++) {
        h_kernel<<<BATCH * 32, THREADS, smem>>>(state_re, state_im, l);
        l_kernel<<<BATCH * 32, THREADS, smem>>>(l, l == 2);
    }
    head_kernel<<<1, BATCH>>>(head_w, head_b, out);
}

// round 10
// speedup vs baseline: 1.4065x; 1.0028x over previous
#include <cuda_runtime.h>

#define NW      18
#define DIM     (1 << 18)
#define BATCH   64
#define THREADS 512
#define TILE    8192           // amplitudes per CTA (u64 re/im pair -> 64 KB smem)
#define NACC    14             // 13 masked sums (bits 0..12) + total prob

typedef unsigned long long u64;
typedef ulonglong2 u64x2;

// Ping-pong state buffers (128 MB each). h: reads input/g_b, writes g_a.
// l: reads g_a, writes g_b (or fused exp-val on last layer).
__device__ __align__(16) u64 g_a[(size_t)BATCH * DIM];
__device__ __align__(16) u64 g_b[(size_t)BATCH * DIM];
__device__ float2 g_ry[3][NW];          // cos(th_y/2), sin(th_y/2)
__device__ u64    g_phz_h[3][256];      // deferred RZ phase e^{-iA}, h rotation bits
__device__ u64    g_phz_l[3][1024];     // deferred RZ phase e^{-iA}, l rotation bits
__device__ float  g_part[BATCH * 32 * NACC];

// ---- packed f32x2 helpers ---------------------------------------------------
static __device__ __forceinline__ u64 pk2(float x, float y) {
    u64 r; asm("mov.b64 %0,{%1,%2};" : "=l"(r) : "f"(x), "f"(y)); return r;
}
static __device__ __forceinline__ void up2(u64 a, float& x, float& y) {
    asm("mov.b64 {%0,%1},%2;" : "=f"(x), "=f"(y) : "l"(a));
}
static __device__ __forceinline__ u64 fma2_(u64 a, u64 b, u64 c) {
    u64 r; asm("fma.rn.f32x2 %0,%1,%2,%3;" : "=l"(r) : "l"(a), "l"(b), "l"(c)); return r;
}
static __device__ __forceinline__ u64 mul2_(u64 a, u64 b) {
    u64 r; asm("mul.rn.f32x2 %0,%1,%2;" : "=l"(r) : "l"(a), "l"(b)); return r;
}

// ---------------------------------------------------------------------------
__global__ void prep_kernel(const float* __restrict__ params) {
    int t = threadIdx.x;
    if (t < 3 * NW) {
        int l = t / NW, w = t % NW;
        float cy, sy;
        sincosf(0.5f * params[l * 36 + w], &sy, &cy);
        g_ry[l][w] = make_float2(cy, sy);
    }
    // h tables: idx bit j (0..7) <-> global bit 10+j <-> wire 7-j
    for (int i = t; i < 3 * 256; i += blockDim.x) {
        int l = i >> 8, idx = i & 255;
        float A = 0.f;
        for (int j = 0; j < 8; j++)
            if (!((idx >> j) & 1)) A += params[l * 36 + NW + (7 - j)];
        float s, c; sincosf(A, &s, &c);
        g_phz_h[l][idx] = pk2(c, -s);
    }
    // l tables: idx bit j (0..9) <-> global bit j <-> wire 17-j
    for (int i = t; i < 3 * 1024; i += blockDim.x) {
        int l = i >> 10, idx = i & 1023;
        float A = 0.f;
        for (int j = 0; j < 10; j++)
            if (!((idx >> j) & 1)) A += params[l * 36 + NW + (17 - j)];
        float s, c; sincosf(A, &s, &c);
        g_phz_l[l][idx] = pk2(c, -s);
    }
}

// RY on a register pair (A: bit=0, B: bit=1).
static __device__ __forceinline__ void rp2y(u64& A, u64& B, u64 cy2, u64 sy2, u64 msy2) {
    u64 nA = fma2_(cy2, A, mul2_(msy2, B));   // A' = cy*A - sy*B
    u64 nB = fma2_(sy2, A, mul2_(cy2,  B));   // B' = sy*A + cy*B
    A = nA; B = nB;
}

// RY where the pair partner lives in lane ^ d.
static __device__ __forceinline__ void shroty(u64& v, u64 cy2, u64 sgn2, int d) {
    float vx, vy; up2(v, vx, vy);
    float ox = __shfl_xor_sync(0xffffffffu, vx, d);
    float oy = __shfl_xor_sync(0xffffffffu, vy, d);
    v = fma2_(cy2, v, mul2_(sgn2, pk2(ox, oy)));
}

// v * (pc + i*ps), p = pk2(pc, ps).
static __device__ __forceinline__ u64 cmulp(u64 v, u64 p) {
    float x, y, pc, ps; up2(v, x, y); up2(p, pc, ps);
    return pk2(fmaf(-y, ps, x * pc), fmaf(x, ps, y * pc));
}

// RY over register-index bit `stride` on both halves of the bit-0 pairs.
static __device__ __forceinline__ void rotpairs(u64* vl, u64* vh, int stride, float2 W) {
    u64 c = pk2(W.x, W.x), s = pk2(W.y, W.y), m = pk2(-W.y, -W.y);
#pragma unroll
    for (int i = 0; i < 8; i++)
        if (!(i & stride)) {
            rp2y(vl[i], vl[i | stride], c, s, m);
            rp2y(vh[i], vh[i | stride], c, s, m);
        }
}

// h-kernel SMEM swizzle: XOR bits 1..4 with bits 5..8 (preserves bit 0 pairs;
// swz(e)^2 == swz(e^2)).
static __device__ __forceinline__ int swz(int e) { return e ^ (((e >> 5) & 15) << 1); }

// ---------------------------------------------------------------------------
// H kernel: RYs on global bits 10..17 (wires 0..7) + one deferred phase.
// Tile bits {0..4} u {10..17}; chunk = bits 5..9. Read folds prior layer's
// low CNOT chain segment (targets 0..11). The fold maps bit-0 pairs to
// aligned bit-0 pairs (shared fold word f; order swapped iff f&1 == t&1),
// so ALL global and SMEM traffic is 128-bit.
// Compute layout: bit0 pair in-reg, e[1..4]=wrp, e[5..9]=lane (g10..14, shfl),
// e[10..12]=reg (g15..17).
__global__ __launch_bounds__(THREADS, 2)
void h_kernel(const float* __restrict__ in_re, const float* __restrict__ in_im, int layer) {
    extern __shared__ u64 sm[];
    const int t = threadIdx.x, lane = t & 31, wrp = t >> 5;
    const int b = blockIdx.x >> 5, chunk = blockIdx.x & 31;
    const size_t base = (size_t)b * DIM;

    if (layer == 0) {
#pragma unroll
        for (int i = 0; i < 4; i++) {
            int e4 = (i * THREADS + t) * 4;                  // 4 consecutive amps
            int a = (e4 & 31) | (chunk << 5) | ((e4 >> 5) << 10);
            float4 r4 = *(const float4*)(in_re + base + a);
            float4 i4 = *(const float4*)(in_im + base + a);
            int s0 = swz(e4);
            u64x2 p0; p0.x = pk2(r4.x, i4.x); p0.y = pk2(r4.y, i4.y);
            u64x2 p1; p1.x = pk2(r4.z, i4.z); p1.y = pk2(r4.w, i4.w);
            *(u64x2*)&sm[s0]     = p0;
            *(u64x2*)&sm[s0 ^ 2] = p1;
        }
    } else {
        const int swapflag = t & 1;                          // == f&1 for all i
#pragma unroll
        for (int i = 0; i < 8; i++) {
            int e = (i * THREADS + t) * 2;                   // pair base (bit0=0)
            int a = (e & 31) | (chunk << 5) | ((e >> 5) << 10);
            int f = (a >> 1) & 0x0FFF;                       // fold: prior chain C(12..1)
            int s = (a ^ f) & ~1;
            u64x2 p = *(const u64x2*)&g_b[base + s];
            u64x2 q;
            q.x = swapflag ? p.y : p.x;
            q.y = swapflag ? p.x : p.y;
            *(u64x2*)&sm[swz(e)] = q;
        }
    }
    __syncthreads();

    u64 vl[8], vh[8];
#pragma unroll
    for (int r = 0; r < 8; r++) {
        u64x2 p = *(u64x2*)&sm[swz((wrp << 1) | (lane << 5) | (r << 10))];
        vl[r] = p.x; vh[r] = p.y;
    }
#pragma unroll
    for (int q = 0; q < 5; q++) {                   // g10..14 = wires 7..3
        float2 W = g_ry[layer][7 - q];
        float sgn = ((lane >> q) & 1) ? W.y : -W.y;
        u64 cy2 = pk2(W.x, W.x), sgn2 = pk2(sgn, sgn);
#pragma unroll
        for (int r = 0; r < 8; r++) { shroty(vl[r], cy2, sgn2, 1 << q); shroty(vh[r], cy2, sgn2, 1 << q); }
    }
    rotpairs(vl, vh, 1, g_ry[layer][2]);            // g15 = wire 2
    rotpairs(vl, vh, 2, g_ry[layer][1]);            // g16 = wire 1
    rotpairs(vl, vh, 4, g_ry[layer][0]);            // g17 = wire 0
    if (layer != 2) {                               // deferred RZ phase, shared per pair
#pragma unroll
        for (int r = 0; r < 8; r++) {
            u64 ph = g_phz_h[layer][lane | (r << 5)];
            vl[r] = cmulp(vl[r], ph); vh[r] = cmulp(vh[r], ph);
        }
    }
#pragma unroll
    for (int r = 0; r < 8; r++) {
        u64x2 p; p.x = vl[r]; p.y = vh[r];
        *(u64x2*)&sm[swz((wrp << 1) | (lane << 5) | (r << 10))] = p;
    }
    __syncthreads();

#pragma unroll
    for (int i = 0; i < 8; i++) {
        int e = (i * THREADS + t) * 2;
        u64x2 p = *(u64x2*)&sm[swz(e)];
        int a = (e & 31) | (chunk << 5) | ((e >> 5) << 10);
        *(u64x2*)&g_a[base + a] = p;
    }
}

// ---------------------------------------------------------------------------
// L kernel: RYs on global bits 0..9 (wires 17..8) + one deferred phase.
// Tile = contiguous bits 0..12; chunk = bits 13..17 (blockIdx REVERSED for
// L2 reuse). Read folds this layer's high chain segment (targets 12..16 —
// bit0 pairs survive -> LDG.128). Phase 1: bit0 intra (wire 17, no shfl),
// bits 1..5 = lane (wires 16..12), bits 6..8 = regs (wires 11..9). One
// 128-bit SMEM exchange. Phase 2: bit 9 (wire 8) in regs, then phase+store
// (or fused exp-val; phase cancels in |amp|^2 on the last layer).
__global__ __launch_bounds__(THREADS, 2)
void l_kernel(int layer, int last) {
    extern __shared__ u64 sm[];
    const int t = threadIdx.x, lane = t & 31, wrp = t >> 5;
    const int rbi = (BATCH * 32 - 1) - blockIdx.x;       // boustrophedon
    const int b = rbi >> 5, chunk = rbi & 31;
    const size_t base = (size_t)b * DIM;

    u64 vl[8], vh[8];
#pragma unroll
    for (int r = 0; r < 8; r++) {
        int e = (wrp << 9) | (r << 6) | (lane << 1);
        int a = (chunk << 13) | e;
        a ^= (a >> 1) & 0x1F000;                // fold: this layer chain C(17..13)
        u64x2 p = *(const u64x2*)&g_a[base + a];
        vl[r] = p.x; vh[r] = p.y;
    }
    {   // bit 0 = wire 17: intra-pair, zero shfl
        float2 W = g_ry[layer][17];
        u64 c = pk2(W.x, W.x), s = pk2(W.y, W.y), m = pk2(-W.y, -W.y);
#pragma unroll
        for (int r = 0; r < 8; r++) rp2y(vl[r], vh[r], c, s, m);
    }
#pragma unroll
    for (int q = 0; q < 5; q++) {               // e[1+q] = g bit 1+q = wire 16-q
        float2 W = g_ry[layer][16 - q];
        float sgn = ((lane >> q) & 1) ? W.y : -W.y;
        u64 cy2 = pk2(W.x, W.x), sgn2 = pk2(sgn, sgn);
#pragma unroll
        for (int r = 0; r < 8; r++) { shroty(vl[r], cy2, sgn2, 1 << q); shroty(vh[r], cy2, sgn2, 1 << q); }
    }
    rotpairs(vl, vh, 1, g_ry[layer][11]);       // e6 = wire 11
    rotpairs(vl, vh, 2, g_ry[layer][10]);       // e7 = wire 10
    rotpairs(vl, vh, 4, g_ry[layer][9]);        // e8 = wire 9
#pragma unroll
    for (int r = 0; r < 8; r++) {
        u64x2 p; p.x = vl[r]; p.y = vh[r];
        *(u64x2*)&sm[(wrp << 9) | (r << 6) | (lane << 1)] = p;
    }
    __syncthreads();

    // Phase 2: e[9,11,12] in regs, e[6,7,8,10] = wrp.
    u64 wl[8], wh[8];
    const int e2b = (lane << 1) | ((wrp & 7) << 6) | ((wrp >> 3) << 10);
#pragma unroll
    for (int r = 0; r < 8; r++) {
        int e2 = e2b | ((r & 1) << 9) | (((r >> 1) & 1) << 11) | (((r >> 2) & 1) << 12);
        u64x2 p = *(u64x2*)&sm[e2];
        wl[r] = p.x; wh[r] = p.y;
    }
    {   // bit 9 = wire 8: reg-index bit 0
        float2 W = g_ry[layer][8];
        u64 c = pk2(W.x, W.x), s = pk2(W.y, W.y), m = pk2(-W.y, -W.y);
#pragma unroll
        for (int i = 0; i < 8; i += 2) { rp2y(wl[i], wl[i | 1], c, s, m); rp2y(wh[i], wh[i | 1], c, s, m); }
    }

    if (!last) {
#pragma unroll
        for (int r = 0; r < 8; r++) {
            int e2 = e2b | ((r & 1) << 9) | (((r >> 1) & 1) << 11) | (((r >> 2) & 1) << 12);
            u64x2 p;
            p.x = cmulp(wl[r], g_phz_l[layer][e2 & 1023]);        // pair halves differ in bit 0
            p.y = cmulp(wh[r], g_phz_l[layer][(e2 | 1) & 1023]);
            *(u64x2*)&g_b[base + (size_t)((chunk << 13) | e2)] = p;
        }
    } else {
        float acc[NACC];
#pragma unroll
        for (int i = 0; i < NACC; i++) acc[i] = 0.f;
#pragma unroll
        for (int r = 0; r < 8; r++) {
            int e2 = e2b | ((r & 1) << 9) | (((r >> 1) & 1) << 11) | (((r >> 2) & 1) << 12);
            float lx, ly, hx, hy;
            up2(wl[r], lx, ly); up2(wh[r], hx, hy);
            float prl = lx * lx + ly * ly;
            float prh = hx * hx + hy * hy;
            float sum = prl + prh, dif = prl - prh;
            int p = e2;                           // suffix parity: bit k = XOR e[k..12]
            p ^= p >> 1; p ^= p >> 2; p ^= p >> 4; p ^= p >> 8;
            acc[0] += (p & 1) ? -dif : dif;       // halves differ only in parity bit 0
#pragma unroll
            for (int k = 1; k < 13; k++)
                acc[k] += ((p >> k) & 1) ? -sum : sum;
            acc[13] += sum;
        }
#pragma unroll
        for (int i = 0; i < NACC; i++)
#pragma unroll
            for (int o = 16; o > 0; o >>= 1)
                acc[i] += __shfl_xor_sync(0xffffffffu, acc[i], o);
        __syncthreads();
        float* red = (float*)sm;
        if (lane == 0)
#pragma unroll
            for (int i = 0; i < NACC; i++) red[wrp * NACC + i] = acc[i];
        __syncthreads();
        if (t < NACC) {
            float s = 0.f;
            for (int w2 = 0; w2 < 16; w2++) s += red[w2 * NACC + t];
            g_part[(b * 32 + chunk) * NACC + t] = s;
        }
    }
}

// ---------------------------------------------------------------------------
__global__ void head_kernel(const float* __restrict__ head_w,
                            const float* __restrict__ head_b,
                            float* __restrict__ out) {
    int b = threadIdx.x;
    if (b >= BATCH) return;
    float fw[NW];
#pragma unroll
    for (int w = 0; w < NW; w++) fw[w] = 0.f;
    for (int c = 0; c < 32; c++) {
        const float* pp = &g_part[(b * 32 + c) * NACC];
#pragma unroll
        for (int k = 0; k < 13; k++) fw[17 - k] += pp[k];    // in-tile masks
        float sp = pp[13];
#pragma unroll
        for (int k = 13; k < 18; k++)                        // chunk-bit signs
            fw[17 - k] += ((c >> (k - 13)) & 1) ? -sp : sp;
    }
    float o = head_b[0];
#pragma unroll
    for (int w = 0; w < NW; w++) o += fw[w] * head_w[w];
    out[b] = o;
}

// ---------------------------------------------------------------------------
extern "C" void kernel_launch(void* const* d_in, const int* in_sizes, int n_in,
                              void* d_out, int out_size) {
    const float* state_re = (const float*)d_in[0];
    const float* state_im = (const float*)d_in[1];
    const float* params   = (const float*)d_in[2];
    const float* head_w   = (const float*)d_in[3];
    const float* head_b   = (const float*)d_in[4];
    float* out = (float*)d_out;

    const int smem = TILE * sizeof(u64);   // 64 KB
    cudaFuncSetAttribute(h_kernel, cudaFuncAttributeMaxDynamicSharedMemorySize, smem);
    cudaFuncSetAttribute(l_kernel, cudaFuncAttributeMaxDynamicSharedMemorySize, smem);

    prep_kernel<<<1, 1024>>>(params);
    for (int l = 0; l < 3; l++) {
        h_kernel<<<BATCH * 32, THREADS, smem>>>(state_re, state_im, l);
        l_kernel<<<BATCH * 32, THREADS, smem>>>(l, l == 2);
    }
    head_kernel<<<1, BATCH>>>(head_w, head_b, out);
}

// round 11
// speedup vs baseline: 1.4213x; 1.0105x over previous
#include <cuda_runtime.h>

#define NW      18
#define DIM     (1 << 18)
#define BATCH   64
#define THREADS 512
#define TILE    8192           // amplitudes per CTA (u64 re/im pair -> 64 KB smem)
#define NACC    14             // 13 masked sums (bits 0..12) + total prob

typedef unsigned long long u64;
typedef ulonglong2 u64x2;

// Ping-pong state buffers (128 MB each). h: reads input/g_b, writes g_a.
// l: reads g_a, writes g_b (or fused exp-val on last layer).
// Convention: g_b holds the S_L-PERMUTED state (l applies its layer's low
// CNOT chain at write time), so h's read is a plain contiguous stream.
__device__ __align__(16) u64 g_a[(size_t)BATCH * DIM];
__device__ __align__(16) u64 g_b[(size_t)BATCH * DIM];
__device__ float2 g_ry[3][NW];          // cos(th_y/2), sin(th_y/2)
__device__ u64    g_phz_h[3][256];      // deferred RZ phase e^{-iA}, h rotation bits
__device__ u64    g_phz_l[3][1024];     // deferred RZ phase e^{-iA}, l rotation bits
__device__ float  g_part[BATCH * 32 * NACC];

// ---- packed f32x2 helpers ---------------------------------------------------
static __device__ __forceinline__ u64 pk2(float x, float y) {
    u64 r; asm("mov.b64 %0,{%1,%2};" : "=l"(r) : "f"(x), "f"(y)); return r;
}
static __device__ __forceinline__ void up2(u64 a, float& x, float& y) {
    asm("mov.b64 {%0,%1},%2;" : "=f"(x), "=f"(y) : "l"(a));
}
static __device__ __forceinline__ u64 fma2_(u64 a, u64 b, u64 c) {
    u64 r; asm("fma.rn.f32x2 %0,%1,%2,%3;" : "=l"(r) : "l"(a), "l"(b), "l"(c)); return r;
}
static __device__ __forceinline__ u64 mul2_(u64 a, u64 b) {
    u64 r; asm("mul.rn.f32x2 %0,%1,%2;" : "=l"(r) : "l"(a), "l"(b)); return r;
}

// ---------------------------------------------------------------------------
__global__ void prep_kernel(const float* __restrict__ params) {
    int t = threadIdx.x;
    if (t < 3 * NW) {
        int l = t / NW, w = t % NW;
        float cy, sy;
        sincosf(0.5f * params[l * 36 + w], &sy, &cy);
        g_ry[l][w] = make_float2(cy, sy);
    }
    // h tables: idx bit j (0..7) <-> global bit 10+j <-> wire 7-j
    for (int i = t; i < 3 * 256; i += blockDim.x) {
        int l = i >> 8, idx = i & 255;
        float A = 0.f;
        for (int j = 0; j < 8; j++)
            if (!((idx >> j) & 1)) A += params[l * 36 + NW + (7 - j)];
        float s, c; sincosf(A, &s, &c);
        g_phz_h[l][idx] = pk2(c, -s);
    }
    // l tables: idx bit j (0..9) <-> global bit j <-> wire 17-j
    for (int i = t; i < 3 * 1024; i += blockDim.x) {
        int l = i >> 10, idx = i & 1023;
        float A = 0.f;
        for (int j = 0; j < 10; j++)
            if (!((idx >> j) & 1)) A += params[l * 36 + NW + (17 - j)];
        float s, c; sincosf(A, &s, &c);
        g_phz_l[l][idx] = pk2(c, -s);
    }
}

// RY on a register pair (A: bit=0, B: bit=1).
static __device__ __forceinline__ void rp2y(u64& A, u64& B, u64 cy2, u64 sy2, u64 msy2) {
    u64 nA = fma2_(cy2, A, mul2_(msy2, B));   // A' = cy*A - sy*B
    u64 nB = fma2_(sy2, A, mul2_(cy2,  B));   // B' = sy*A + cy*B
    A = nA; B = nB;
}

// RY where the pair partner lives in lane ^ d.
static __device__ __forceinline__ void shroty(u64& v, u64 cy2, u64 sgn2, int d) {
    float vx, vy; up2(v, vx, vy);
    float ox = __shfl_xor_sync(0xffffffffu, vx, d);
    float oy = __shfl_xor_sync(0xffffffffu, vy, d);
    v = fma2_(cy2, v, mul2_(sgn2, pk2(ox, oy)));
}

// v * (pc + i*ps), p = pk2(pc, ps).
static __device__ __forceinline__ u64 cmulp(u64 v, u64 p) {
    float x, y, pc, ps; up2(v, x, y); up2(p, pc, ps);
    return pk2(fmaf(-y, ps, x * pc), fmaf(x, ps, y * pc));
}

// RY over register-index bit `stride` on both halves of the bit-0 pairs.
static __device__ __forceinline__ void rotpairs(u64* vl, u64* vh, int stride, float2 W) {
    u64 c = pk2(W.x, W.x), s = pk2(W.y, W.y), m = pk2(-W.y, -W.y);
#pragma unroll
    for (int i = 0; i < 8; i++)
        if (!(i & stride)) {
            rp2y(vl[i], vl[i | stride], c, s, m);
            rp2y(vh[i], vh[i | stride], c, s, m);
        }
}

// h-kernel SMEM swizzle: XOR bits 1..4 with bits 5..8 (preserves bit 0 pairs;
// swz(e)^2 == swz(e^2)).
static __device__ __forceinline__ int swz(int e) { return e ^ (((e >> 5) & 15) << 1); }

// ---------------------------------------------------------------------------
// H kernel: RYs on global bits 10..17 (wires 0..7) + one deferred phase.
// Tile bits {0..4} u {10..17}; chunk = bits 5..9. g_b already holds the
// S_L-permuted state (l applied its chain at write) -> plain contiguous read.
// Compute layout: bit0 pair in-reg, e[1..4]=wrp, e[5..9]=lane (g10..14, shfl),
// e[10..12]=reg (g15..17).
__global__ __launch_bounds__(THREADS, 2)
void h_kernel(const float* __restrict__ in_re, const float* __restrict__ in_im, int layer) {
    extern __shared__ u64 sm[];
    const int t = threadIdx.x, lane = t & 31, wrp = t >> 5;
    const int b = blockIdx.x >> 5, chunk = blockIdx.x & 31;
    const size_t base = (size_t)b * DIM;

    if (layer == 0) {
#pragma unroll
        for (int i = 0; i < 4; i++) {
            int e4 = (i * THREADS + t) * 4;                  // 4 consecutive amps
            int a = (e4 & 31) | (chunk << 5) | ((e4 >> 5) << 10);
            float4 r4 = *(const float4*)(in_re + base + a);
            float4 i4 = *(const float4*)(in_im + base + a);
            int s0 = swz(e4);
            u64x2 p0; p0.x = pk2(r4.x, i4.x); p0.y = pk2(r4.y, i4.y);
            u64x2 p1; p1.x = pk2(r4.z, i4.z); p1.y = pk2(r4.w, i4.w);
            *(u64x2*)&sm[s0]     = p0;
            *(u64x2*)&sm[s0 ^ 2] = p1;
        }
    } else {
#pragma unroll
        for (int i = 0; i < 8; i++) {
            int e = (i * THREADS + t) * 2;                   // pair base (bit0=0)
            int a = (e & 31) | (chunk << 5) | ((e >> 5) << 10);
            *(u64x2*)&sm[swz(e)] = *(const u64x2*)&g_b[base + a];
        }
    }
    __syncthreads();

    u64 vl[8], vh[8];
#pragma unroll
    for (int r = 0; r < 8; r++) {
        u64x2 p = *(u64x2*)&sm[swz((wrp << 1) | (lane << 5) | (r << 10))];
        vl[r] = p.x; vh[r] = p.y;
    }
#pragma unroll
    for (int q = 0; q < 5; q++) {                   // g10..14 = wires 7..3
        float2 W = g_ry[layer][7 - q];
        float sgn = ((lane >> q) & 1) ? W.y : -W.y;
        u64 cy2 = pk2(W.x, W.x), sgn2 = pk2(sgn, sgn);
#pragma unroll
        for (int r = 0; r < 8; r++) { shroty(vl[r], cy2, sgn2, 1 << q); shroty(vh[r], cy2, sgn2, 1 << q); }
    }
    rotpairs(vl, vh, 1, g_ry[layer][2]);            // g15 = wire 2
    rotpairs(vl, vh, 2, g_ry[layer][1]);            // g16 = wire 1
    rotpairs(vl, vh, 4, g_ry[layer][0]);            // g17 = wire 0
    if (layer != 2) {                               // deferred RZ phase, shared per pair
#pragma unroll
        for (int r = 0; r < 8; r++) {
            u64 ph = g_phz_h[layer][lane | (r << 5)];
            vl[r] = cmulp(vl[r], ph); vh[r] = cmulp(vh[r], ph);
        }
    }
#pragma unroll
    for (int r = 0; r < 8; r++) {
        u64x2 p; p.x = vl[r]; p.y = vh[r];
        *(u64x2*)&sm[swz((wrp << 1) | (lane << 5) | (r << 10))] = p;
    }
    __syncthreads();

#pragma unroll
    for (int i = 0; i < 8; i++) {
        int e = (i * THREADS + t) * 2;
        u64x2 p = *(u64x2*)&sm[swz(e)];
        int a = (e & 31) | (chunk << 5) | ((e >> 5) << 10);
        *(u64x2*)&g_a[base + a] = p;
    }
}

// ---------------------------------------------------------------------------
// L kernel: RYs on global bits 0..9 (wires 17..8) + one deferred phase.
// Tile = contiguous bits 0..12; chunk = bits 13..17 (blockIdx REVERSED for
// L2 reuse). Read folds this layer's high chain segment (targets 12..16 —
// whole-4KB-block relocation, stays coalesced). Phase 1: bit0 intra (wire 17),
// bits 1..5 = lane (wires 16..12), bits 6..8 = regs (wires 11..9); one
// 128-bit SMEM exchange. Phase 2 (!last): for each output quad
// {j, j^1, j^0x3FF, j^0x3FE} (perm-linear: perm(0x3FF)=512, perm(1)=1),
// gather SMEM pairs at k0=perm(j) (bit9 partner = other load), apply wire-8
// rotation + deferred phase at index k, and write g_b CONTIGUOUSLY -> next
// h reads a plain stream. Last layer: wire-8 rot + fused exp-val (S_L folded
// into suffix-parity signs; phase cancels in |amp|^2).
__global__ __launch_bounds__(THREADS, 2)
void l_kernel(int layer, int last) {
    extern __shared__ u64 sm[];
    const int t = threadIdx.x, lane = t & 31, wrp = t >> 5;
    const int rbi = (BATCH * 32 - 1) - blockIdx.x;       // boustrophedon
    const int b = rbi >> 5, chunk = rbi & 31;
    const size_t base = (size_t)b * DIM;

    u64 vl[8], vh[8];
#pragma unroll
    for (int r = 0; r < 8; r++) {
        int e = (wrp << 9) | (r << 6) | (lane << 1);
        int a = (chunk << 13) | e;
        a ^= (a >> 1) & 0x1F000;                // fold: this layer chain C(17..13)
        u64x2 p = *(const u64x2*)&g_a[base + a];
        vl[r] = p.x; vh[r] = p.y;
    }
    {   // bit 0 = wire 17: intra-pair, zero shfl
        float2 W = g_ry[layer][17];
        u64 c = pk2(W.x, W.x), s = pk2(W.y, W.y), m = pk2(-W.y, -W.y);
#pragma unroll
        for (int r = 0; r < 8; r++) rp2y(vl[r], vh[r], c, s, m);
    }
#pragma unroll
    for (int q = 0; q < 5; q++) {               // e[1+q] = g bit 1+q = wire 16-q
        float2 W = g_ry[layer][16 - q];
        float sgn = ((lane >> q) & 1) ? W.y : -W.y;
        u64 cy2 = pk2(W.x, W.x), sgn2 = pk2(sgn, sgn);
#pragma unroll
        for (int r = 0; r < 8; r++) { shroty(vl[r], cy2, sgn2, 1 << q); shroty(vh[r], cy2, sgn2, 1 << q); }
    }
    rotpairs(vl, vh, 1, g_ry[layer][11]);       // e6 = wire 11
    rotpairs(vl, vh, 2, g_ry[layer][10]);       // e7 = wire 10
    rotpairs(vl, vh, 4, g_ry[layer][9]);        // e8 = wire 9
#pragma unroll
    for (int r = 0; r < 8; r++) {
        u64x2 p; p.x = vl[r]; p.y = vh[r];
        *(u64x2*)&sm[(wrp << 9) | (r << 6) | (lane << 1)] = p;
    }
    __syncthreads();

    float2 W8 = g_ry[layer][8];                 // global bit 9 -> wire 8
    const u64 c8 = pk2(W8.x, W8.x), s8 = pk2(W8.y, W8.y), m8 = pk2(-W8.y, -W8.y);

    if (!last) {
        // Quad-based gather: output slot j (bit0=0, bit9=0, 11 free bits).
#pragma unroll
        for (int u = 0; u < 4; u++) {
            int j  = (lane << 1) | (u << 6) | ((wrp & 1) << 8) | ((wrp >> 1) << 10);
            int k0 = j ^ ((j >> 1) & 0xFFF);            // perm: this layer chain C(12..1)
            int sw = k0 & 1;                            // pair-order swap (== bit1 of j)
            int bA = k0 & ~513;                         // bit0=0, bit9=0 base
            u64x2 pA = *(u64x2*)&sm[bA];
            u64x2 pB = *(u64x2*)&sm[bA | 512];
            u64 a0 = sw ? pA.y : pA.x, a1 = sw ? pA.x : pA.y;   // amp[k0&~512], amp[(k0^1)&~512]
            u64 b0 = sw ? pB.y : pB.x, b1 = sw ? pB.x : pB.y;   // amp[k0|512],  amp[(k0^1)|512]
            rp2y(a0, b0, c8, s8, m8);                   // wire-8 rotation (bit 9 pairs)
            rp2y(a1, b1, c8, s8, m8);
            int hi9 = k0 & 512;
            u64 f00 = hi9 ? b0 : a0;                    // phi'[k0]
            u64 f01 = hi9 ? b1 : a1;                    // phi'[k0^1]
            u64 f10 = hi9 ? a0 : b0;                    // phi'[k0^512]
            u64 f11 = hi9 ? a1 : b1;                    // phi'[k0^513]
            int kx = k0 & 1023;
            u64x2 W1, W2;
            W1.x = cmulp(f00, g_phz_l[layer][kx]);          // slot j       (k = k0)
            W1.y = cmulp(f01, g_phz_l[layer][kx ^ 1]);      // slot j^1     (k = k0^1)
            W2.x = cmulp(f11, g_phz_l[layer][kx ^ 513]);    // slot j^0x3FE (k = k0^513)
            W2.y = cmulp(f10, g_phz_l[layer][kx ^ 512]);    // slot j^0x3FF (k = k0^512)
            *(u64x2*)&g_b[base + (size_t)((chunk << 13) | j)] = W1;
            *(u64x2*)&g_b[base + (size_t)((chunk << 13) | (j ^ 0x3FE))] = W2;
        }
    } else {
        // Phase 2 (last): e[9,11,12] in regs, e[6,7,8,10] = wrp.
        u64 wl[8], wh[8];
        const int e2b = (lane << 1) | ((wrp & 7) << 6) | ((wrp >> 3) << 10);
#pragma unroll
        for (int r = 0; r < 8; r++) {
            int e2 = e2b | ((r & 1) << 9) | (((r >> 1) & 1) << 11) | (((r >> 2) & 1) << 12);
            u64x2 p = *(u64x2*)&sm[e2];
            wl[r] = p.x; wh[r] = p.y;
        }
#pragma unroll
        for (int i = 0; i < 8; i += 2) { rp2y(wl[i], wl[i | 1], c8, s8, m8); rp2y(wh[i], wh[i | 1], c8, s8, m8); }

        float acc[NACC];
#pragma unroll
        for (int i = 0; i < NACC; i++) acc[i] = 0.f;
#pragma unroll
        for (int r = 0; r < 8; r++) {
            int e2 = e2b | ((r & 1) << 9) | (((r >> 1) & 1) << 11) | (((r >> 2) & 1) << 12);
            float lx, ly, hx, hy;
            up2(wl[r], lx, ly); up2(wh[r], hx, hy);
            float prl = lx * lx + ly * ly;
            float prh = hx * hx + hy * hy;
            float sum = prl + prh, dif = prl - prh;
            int p = e2;                           // suffix parity: bit k = XOR e[k..12]
            p ^= p >> 1; p ^= p >> 2; p ^= p >> 4; p ^= p >> 8;
            acc[0] += (p & 1) ? -dif : dif;       // halves differ only in parity bit 0
#pragma unroll
            for (int k = 1; k < 13; k++)
                acc[k] += ((p >> k) & 1) ? -sum : sum;
            acc[13] += sum;
        }
#pragma unroll
        for (int i = 0; i < NACC; i++)
#pragma unroll
            for (int o = 16; o > 0; o >>= 1)
                acc[i] += __shfl_xor_sync(0xffffffffu, acc[i], o);
        __syncthreads();
        float* red = (float*)sm;
        if (lane == 0)
#pragma unroll
            for (int i = 0; i < NACC; i++) red[wrp * NACC + i] = acc[i];
        __syncthreads();
        if (t < NACC) {
            float s = 0.f;
            for (int w2 = 0; w2 < 16; w2++) s += red[w2 * NACC + t];
            g_part[(b * 32 + chunk) * NACC + t] = s;
        }
    }
}

// ---------------------------------------------------------------------------
__global__ void head_kernel(const float* __restrict__ head_w,
                            const float* __restrict__ head_b,
                            float* __restrict__ out) {
    int b = threadIdx.x;
    if (b >= BATCH) return;
    float fw[NW];
#pragma unroll
    for (int w = 0; w < NW; w++) fw[w] = 0.f;
    for (int c = 0; c < 32; c++) {
        const float* pp = &g_part[(b * 32 + c) * NACC];
#pragma unroll
        for (int k = 0; k < 13; k++) fw[17 - k] += pp[k];    // in-tile masks
        float sp = pp[13];
#pragma unroll
        for (int k = 13; k < 18; k++)                        // chunk-bit signs
            fw[17 - k] += ((c >> (k - 13)) & 1) ? -sp : sp;
    }
    float o = head_b[0];
#pragma unroll
    for (int w = 0; w < NW; w++) o += fw[w] * head_w[w];
    out[b] = o;
}

// ---------------------------------------------------------------------------
extern "C" void kernel_launch(void* const* d_in, const int* in_sizes, int n_in,
                              void* d_out, int out_size) {
    const float* state_re = (const float*)d_in[0];
    const float* state_im = (const float*)d_in[1];
    const float* params   = (const float*)d_in[2];
    const float* head_w   = (const float*)d_in[3];
    const float* head_b   = (const float*)d_in[4];
    float* out = (float*)d_out;

    const int smem = TILE * sizeof(u64);   // 64 KB
    cudaFuncSetAttribute(h_kernel, cudaFuncAttributeMaxDynamicSharedMemorySize, smem);
    cudaFuncSetAttribute(l_kernel, cudaFuncAttributeMaxDynamicSharedMemorySize, smem);

    prep_kernel<<<1, 1024>>>(params);
    for (int l = 0; l < 3; l++) {
        h_kernel<<<BATCH * 32, THREADS, smem>>>(state_re, state_im, l);
        l_kernel<<<BATCH * 32, THREADS, smem>>>(l, l == 2);
    }
    head_kernel<<<1, BATCH>>>(head_w, head_b, out);
}